// round 9
// baseline (speedup 1.0000x reference)
#include <cuda_runtime.h>
#include <cuda_bf16.h>
#include <cstdint>

// Problem constants (B=2, T=2048 -> N=4096 tokens)
#define NTOK 4096
#define DDIM 1024
#define HDIM 4096
#define NEXP 8
#define NSLOT (NTOK * 2)

// ---------------- scratch (static device globals; no allocation) ------------
__device__ __nv_bfloat16 g_xhi[(size_t)NTOK * DDIM];
__device__ __nv_bfloat16 g_xlo[(size_t)NTOK * DDIM];
__device__ __nv_bfloat16 g_fchi[(size_t)NEXP * HDIM * DDIM];
__device__ __nv_bfloat16 g_fclo[(size_t)NEXP * HDIM * DDIM];
__device__ __nv_bfloat16 g_pjhi[(size_t)NEXP * DDIM * HDIM];
__device__ __nv_bfloat16 g_pjlo[(size_t)NEXP * DDIM * HDIM];
__device__ __nv_bfloat16 g_hhi[(size_t)NSLOT * HDIM];
__device__ __nv_bfloat16 g_hlo[(size_t)NSLOT * HDIM];
__device__ float g_yp[(size_t)NSLOT * DDIM];
__device__ int   g_eidx[NSLOT];
__device__ float g_ew[NSLOT];
__device__ int   g_pos[NSLOT];
__device__ int   g_slotof[NSLOT];
__device__ int   g_perm[NSLOT];
__device__ int   g_cnt[NEXP];
__device__ int   g_base[NEXP];
__device__ float g_sump[NEXP];
__device__ float g_loss;

// ---------------- helpers ----------------------------------------------------
__device__ __forceinline__ uint32_t smem_u32(const void* p) {
    uint32_t a;
    asm("{ .reg .u64 t; cvta.to.shared.u64 t, %1; cvt.u32.u64 %0, t; }"
        : "=r"(a) : "l"(p));
    return a;
}

// pack two fp32 -> bf16x2 (x -> low half, y -> high half)
__device__ __forceinline__ uint32_t pack2(float x, float y) {
    uint32_t r;
    asm("cvt.rn.bf16x2.f32 %0, %1, %2;" : "=r"(r) : "f"(y), "f"(x));
    return r;
}

__device__ __forceinline__ void split2(float x, float y, uint32_t& hi, uint32_t& lo) {
    hi = pack2(x, y);
    float hx = __uint_as_float(hi << 16);
    float hy = __uint_as_float(hi & 0xFFFF0000u);
    lo = pack2(x - hx, y - hy);
}

// ---------------- precision-split conversion ---------------------------------
__global__ void convert_kernel(const float* __restrict__ src,
                               __nv_bfloat16* __restrict__ hi,
                               __nv_bfloat16* __restrict__ lo, int n4) {
    int i = blockIdx.x * blockDim.x + threadIdx.x;
    int stride = gridDim.x * blockDim.x;
    for (; i < n4; i += stride) {
        float4 v = ((const float4*)src)[i];
        uint32_t h0, l0, h1, l1;
        split2(v.x, v.y, h0, l0);
        split2(v.z, v.w, h1, l1);
        ((uint2*)hi)[i] = make_uint2(h0, h1);
        ((uint2*)lo)[i] = make_uint2(l0, l1);
    }
}

// ---------------- init -------------------------------------------------------
__global__ void init_kernel() {
    int t = threadIdx.x;
    if (t < NEXP) { g_cnt[t] = 0; g_sump[t] = 0.0f; }
}

// ---------------- gating: 1 warp per token -----------------------------------
__global__ void gating_kernel(const float* __restrict__ x,
                              const float* __restrict__ wg) {
    int warp = (blockIdx.x * blockDim.x + threadIdx.x) >> 5;
    int lane = threadIdx.x & 31;
    if (warp >= NTOK) return;
    const float* xr = x + (size_t)warp * DDIM;

    float acc[NEXP];
#pragma unroll
    for (int e = 0; e < NEXP; e++) acc[e] = 0.0f;

    for (int d = lane; d < DDIM; d += 32) {
        float xv = xr[d];
#pragma unroll
        for (int e = 0; e < NEXP; e++) acc[e] += xv * wg[e * DDIM + d];
    }
#pragma unroll
    for (int e = 0; e < NEXP; e++) {
#pragma unroll
        for (int o = 16; o > 0; o >>= 1)
            acc[e] += __shfl_xor_sync(0xFFFFFFFFu, acc[e], o);
    }

    if (lane == 0) {
        float mx = acc[0];
#pragma unroll
        for (int e = 1; e < NEXP; e++) mx = fmaxf(mx, acc[e]);
        float p[NEXP], s = 0.0f;
#pragma unroll
        for (int e = 0; e < NEXP; e++) { p[e] = __expf(acc[e] - mx); s += p[e]; }
        float inv = 1.0f / s;
#pragma unroll
        for (int e = 0; e < NEXP; e++) p[e] *= inv;

#pragma unroll
        for (int e = 0; e < NEXP; e++) atomicAdd(&g_sump[e], p[e]);

        int i0 = 0;
#pragma unroll
        for (int e = 1; e < NEXP; e++) if (p[e] > p[i0]) i0 = e;
        int i1 = (i0 == 0) ? 1 : 0;
#pragma unroll
        for (int e = 0; e < NEXP; e++) if (e != i0 && p[e] > p[i1]) i1 = e;

        float w0 = p[i0], w1 = p[i1];
        float rinv = 1.0f / (w0 + w1);
        w0 *= rinv; w1 *= rinv;

        g_eidx[2 * warp + 0] = i0;
        g_eidx[2 * warp + 1] = i1;
        g_ew[2 * warp + 0] = w0;
        g_ew[2 * warp + 1] = w1;
        g_pos[2 * warp + 0] = atomicAdd(&g_cnt[i0], 1);
        g_pos[2 * warp + 1] = atomicAdd(&g_cnt[i1], 1);
    }
}

// ---------------- prefix + balance loss --------------------------------------
__global__ void prefix_kernel() {
    if (threadIdx.x == 0) {
        int b = 0;
        float loss = 0.0f;
        for (int e = 0; e < NEXP; e++) {
            g_base[e] = b;
            b += g_cnt[e];
            loss += g_sump[e] * (float)g_cnt[e];
        }
        g_loss = loss * (float)NEXP / ((float)NTOK * (float)NTOK);
    }
}

// ---------------- scatter ----------------------------------------------------
__global__ void scatter_kernel() {
    int t = blockIdx.x * blockDim.x + threadIdx.x;
    if (t < NSLOT) {
        int e = g_eidx[t];
        int slot = g_base[e] + g_pos[t];
        g_slotof[t] = slot;
        g_perm[slot] = t >> 1;
    }
}

// ---------------- bf16x3 mma.sync grouped GEMM, cp.async pipelined -----------
// D[m,n] = sum_k A[m,k]*B[n,k] with A,B pre-split into bf16 hi/lo.
// acc += Ahi*Bhi + Alo*Bhi + Ahi*Blo.  CTA tile 128x128, K chunk 32,
// 8 warps 4(M)x2(N), warp tile 32x64.  Double-buffered SMEM via cp.async.
#define TM 128
#define TN 128
#define TKC 32
#define SROW 40                    // halves per smem row (80B, conflict-free)
#define A_HI 0
#define A_LO 10240                 // 128*80
#define B_HI 20480
#define B_LO 30720
#define SSTG 40960
#define SMEM_DYN (2 * SSTG)        // 81920

#define CPA16(dst, src, sz) \
    asm volatile("cp.async.cg.shared.global [%0], [%1], 16, %2;" \
                 :: "r"(dst), "l"(src), "r"(sz))
#define CPA_COMMIT() asm volatile("cp.async.commit_group;" ::: "memory")
#define CPA_WAIT1() asm volatile("cp.async.wait_group 1;" ::: "memory")
#define CPA_WAIT0() asm volatile("cp.async.wait_group 0;" ::: "memory")

#define LDSM4(r, addr) \
    asm volatile("ldmatrix.sync.aligned.m8n8.x4.shared.b16 {%0,%1,%2,%3}, [%4];" \
                 : "=r"((r)[0]), "=r"((r)[1]), "=r"((r)[2]), "=r"((r)[3]) \
                 : "r"(addr))

#define MMA16816(c, a, b0_, b1_) \
    asm volatile("mma.sync.aligned.m16n8k16.row.col.f32.bf16.bf16.f32 " \
                 "{%0,%1,%2,%3}, {%4,%5,%6,%7}, {%8,%9}, {%0,%1,%2,%3};" \
                 : "+f"((c)[0]), "+f"((c)[1]), "+f"((c)[2]), "+f"((c)[3]) \
                 : "r"((a)[0]), "r"((a)[1]), "r"((a)[2]), "r"((a)[3]), \
                   "r"(b0_), "r"(b1_))

template <int KD, int ND, bool PH1>
__global__ __launch_bounds__(256, 2)
void gemm_bf16(const __nv_bfloat16* __restrict__ Ahi_,
               const __nv_bfloat16* __restrict__ Alo_,
               const __nv_bfloat16* __restrict__ Bhi_,
               const __nv_bfloat16* __restrict__ Blo_) {
    extern __shared__ __align__(16) unsigned char smem[];
    int e = blockIdx.z;
    int count = g_cnt[e];
    int m0 = blockIdx.y * TM;
    if (m0 >= count) return;
    int n0 = blockIdx.x * TN;
    int base = g_base[e];

    const __nv_bfloat16* Bhi = Bhi_ + (size_t)e * KD * ND;
    const __nv_bfloat16* Blo = Blo_ + (size_t)e * KD * ND;

    int tid = threadIdx.x;
    int lane = tid & 31;
    int wid = tid >> 5;
    int warp_m = wid & 3;
    int warp_n = wid >> 2;
    uint32_t sb = smem_u32(smem);

    // --- cp.async loader mapping (A and B identical: 128 rows x 64B) ---
    int lrow = tid >> 1;                 // tile row 0..127
    int lhalf = tid & 1;                 // which 32B half of the 64B row

    int am = m0 + lrow;
    bool av = am < count;
    int gidx = 0;
    if (av) gidx = PH1 ? g_perm[base + am] : (base + am);
    uint32_t asz = av ? 16u : 0u;
    const __nv_bfloat16* a_hi_src = Ahi_ + (size_t)gidx * KD + lhalf * 16;
    const __nv_bfloat16* a_lo_src = Alo_ + (size_t)gidx * KD + lhalf * 16;
    const __nv_bfloat16* b_hi_src = Bhi + (size_t)(n0 + lrow) * KD + lhalf * 16;
    const __nv_bfloat16* b_lo_src = Blo + (size_t)(n0 + lrow) * KD + lhalf * 16;

    uint32_t row_dst = lrow * (SROW * 2) + lhalf * 32;

    // --- ldmatrix lane addresses (relative to stage base) ---
    uint32_t arow_l = (uint32_t)(warp_m * 32 + (lane & 7) + ((lane >> 3) & 1) * 8);
    uint32_t akoff = (uint32_t)((lane >> 4) * 8);
    uint32_t a_ld = sb + (arow_l * SROW + akoff) * 2;
    uint32_t brow_l = (uint32_t)(warp_n * 64 + (lane & 7) + (lane >> 4) * 8);
    uint32_t bkoff = (uint32_t)(((lane >> 3) & 1) * 8);
    uint32_t b_ld = sb + B_HI + (brow_l * SROW + bkoff) * 2;

    float acc[2][8][4];
#pragma unroll
    for (int i = 0; i < 2; i++)
#pragma unroll
        for (int j = 0; j < 8; j++)
#pragma unroll
            for (int q = 0; q < 4; q++) acc[i][j][q] = 0.0f;

    auto issue = [&](int s, int k0) {
        uint32_t d = sb + s * SSTG + row_dst;
        CPA16(d + A_HI,      a_hi_src + k0,     asz);
        CPA16(d + A_HI + 16, a_hi_src + k0 + 8, asz);
        CPA16(d + A_LO,      a_lo_src + k0,     asz);
        CPA16(d + A_LO + 16, a_lo_src + k0 + 8, asz);
        CPA16(d + B_HI,      b_hi_src + k0,     16u);
        CPA16(d + B_HI + 16, b_hi_src + k0 + 8, 16u);
        CPA16(d + B_LO,      b_lo_src + k0,     16u);
        CPA16(d + B_LO + 16, b_lo_src + k0 + 8, 16u);
    };

    const int NCH = KD / TKC;
    issue(0, 0);
    CPA_COMMIT();

    for (int c = 0; c < NCH; c++) {
        if (c + 1 < NCH) {
            issue((c + 1) & 1, (c + 1) * TKC);
            CPA_COMMIT();
            CPA_WAIT1();
        } else {
            CPA_WAIT0();
        }
        __syncthreads();

        int s = c & 1;
        uint32_t abase = a_ld + s * SSTG;
        uint32_t bbase = b_ld + s * SSTG;
#pragma unroll
        for (int ks = 0; ks < 2; ks++) {
            uint32_t ah0[4], ah1[4], al0[4], al1[4];
            uint32_t aad = abase + ks * 32;
            LDSM4(ah0, aad);
            LDSM4(ah1, aad + 16 * SROW * 2);
            LDSM4(al0, aad + A_LO);
            LDSM4(al1, aad + A_LO + 16 * SROW * 2);
#pragma unroll
            for (int np = 0; np < 4; np++) {
                uint32_t bh[4], bl[4];
                uint32_t bad = bbase + ks * 32 + np * 16 * SROW * 2;
                LDSM4(bh, bad);
                LDSM4(bl, bad + (B_LO - B_HI));

                MMA16816(acc[0][np * 2 + 0], ah0, bh[0], bh[1]);
                MMA16816(acc[0][np * 2 + 0], al0, bh[0], bh[1]);
                MMA16816(acc[0][np * 2 + 0], ah0, bl[0], bl[1]);
                MMA16816(acc[0][np * 2 + 1], ah0, bh[2], bh[3]);
                MMA16816(acc[0][np * 2 + 1], al0, bh[2], bh[3]);
                MMA16816(acc[0][np * 2 + 1], ah0, bl[2], bl[3]);

                MMA16816(acc[1][np * 2 + 0], ah1, bh[0], bh[1]);
                MMA16816(acc[1][np * 2 + 0], al1, bh[0], bh[1]);
                MMA16816(acc[1][np * 2 + 0], ah1, bl[0], bl[1]);
                MMA16816(acc[1][np * 2 + 1], ah1, bh[2], bh[3]);
                MMA16816(acc[1][np * 2 + 1], al1, bh[2], bh[3]);
                MMA16816(acc[1][np * 2 + 1], ah1, bl[2], bl[3]);
            }
        }
        __syncthreads();
    }

    // epilogue
    int g = lane >> 2, t4 = lane & 3;
#pragma unroll
    for (int mt = 0; mt < 2; mt++) {
        int mr = m0 + warp_m * 32 + mt * 16 + g;
#pragma unroll
        for (int nt = 0; nt < 8; nt++) {
            int col = n0 + warp_n * 64 + nt * 8 + 2 * t4;
            float2 v0, v1;
            v0.x = acc[mt][nt][0]; v0.y = acc[mt][nt][1];
            v1.x = acc[mt][nt][2]; v1.y = acc[mt][nt][3];
            if (PH1) {
                v0.x = fmaxf(v0.x, 0.f); v0.x *= v0.x;
                v0.y = fmaxf(v0.y, 0.f); v0.y *= v0.y;
                v1.x = fmaxf(v1.x, 0.f); v1.x *= v1.x;
                v1.y = fmaxf(v1.y, 0.f); v1.y *= v1.y;
                uint32_t h, l;
                if (mr < count) {
                    size_t o = (size_t)(base + mr) * ND + col;
                    split2(v0.x, v0.y, h, l);
                    *(uint32_t*)(g_hhi + o) = h;
                    *(uint32_t*)(g_hlo + o) = l;
                }
                if (mr + 8 < count) {
                    size_t o = (size_t)(base + mr + 8) * ND + col;
                    split2(v1.x, v1.y, h, l);
                    *(uint32_t*)(g_hhi + o) = h;
                    *(uint32_t*)(g_hlo + o) = l;
                }
            } else {
                if (mr < count)
                    *(float2*)(g_yp + (size_t)(base + mr) * ND + col) = v0;
                if (mr + 8 < count)
                    *(float2*)(g_yp + (size_t)(base + mr + 8) * ND + col) = v1;
            }
        }
    }
}

// ---------------- combine ----------------------------------------------------
__global__ void combine_kernel(float* __restrict__ out, int out_size) {
    const int nv = DDIM / 4;
    int t = blockIdx.x * blockDim.x + threadIdx.x;
    if (t < NTOK * nv) {
        int n = t / nv, dv = t % nv;
        int s0 = g_slotof[2 * n], s1 = g_slotof[2 * n + 1];
        float w0 = g_ew[2 * n], w1 = g_ew[2 * n + 1];
        const float4* yp = (const float4*)g_yp;
        float4 a = yp[(size_t)s0 * nv + dv];
        float4 b = yp[(size_t)s1 * nv + dv];
        float4 r;
        r.x = w0 * a.x + w1 * b.x;
        r.y = w0 * a.y + w1 * b.y;
        r.z = w0 * a.z + w1 * b.z;
        r.w = w0 * a.w + w1 * b.w;
        ((float4*)out)[t] = r;
    }
    if (t == 0) {
        for (int idx = NTOK * DDIM; idx < out_size; idx++) out[idx] = g_loss;
    }
}

// ---------------- launch -----------------------------------------------------
extern "C" void kernel_launch(void* const* d_in, const int* in_sizes, int n_in,
                              void* d_out, int out_size) {
    const float* x   = (const float*)d_in[0];
    const float* wg  = (const float*)d_in[1];
    const float* wfc = (const float*)d_in[2];
    const float* wpj = (const float*)d_in[3];
    float* out = (float*)d_out;

    cudaFuncSetAttribute(gemm_bf16<DDIM, HDIM, true>,
                         cudaFuncAttributeMaxDynamicSharedMemorySize, SMEM_DYN);
    cudaFuncSetAttribute(gemm_bf16<HDIM, DDIM, false>,
                         cudaFuncAttributeMaxDynamicSharedMemorySize, SMEM_DYN);

    __nv_bfloat16 *xhi, *xlo, *fchi, *fclo, *pjhi, *pjlo, *hhi, *hlo;
    cudaGetSymbolAddress((void**)&xhi, g_xhi);
    cudaGetSymbolAddress((void**)&xlo, g_xlo);
    cudaGetSymbolAddress((void**)&fchi, g_fchi);
    cudaGetSymbolAddress((void**)&fclo, g_fclo);
    cudaGetSymbolAddress((void**)&pjhi, g_pjhi);
    cudaGetSymbolAddress((void**)&pjlo, g_pjlo);
    cudaGetSymbolAddress((void**)&hhi, g_hhi);
    cudaGetSymbolAddress((void**)&hlo, g_hlo);

    init_kernel<<<1, 32>>>();
    convert_kernel<<<1184, 256>>>(x, xhi, xlo, NTOK * DDIM / 4);
    convert_kernel<<<1184, 256>>>(wfc, fchi, fclo, NEXP * HDIM * DDIM / 4);
    convert_kernel<<<1184, 256>>>(wpj, pjhi, pjlo, NEXP * DDIM * HDIM / 4);
    gating_kernel<<<NTOK / 4, 128>>>(x, wg);
    prefix_kernel<<<1, 32>>>();
    scatter_kernel<<<(NSLOT + 255) / 256, 256>>>();

    dim3 g1(HDIM / TN, NSLOT / TM, NEXP);   // 32 x 64 x 8
    gemm_bf16<DDIM, HDIM, true><<<g1, 256, SMEM_DYN>>>(xhi, xlo, fchi, fclo);

    dim3 g2(DDIM / TN, NSLOT / TM, NEXP);   // 8 x 64 x 8
    gemm_bf16<HDIM, DDIM, false><<<g2, 256, SMEM_DYN>>>(hhi, hlo, pjhi, pjlo);

    combine_kernel<<<(NTOK * DDIM / 4 + 255) / 256, 256>>>(out, out_size);
}

// round 12
// speedup vs baseline: 1.8545x; 1.8545x over previous
#include <cuda_runtime.h>
#include <cuda_fp16.h>
#include <cstdint>

// Problem constants (B=2, T=2048 -> N=4096 tokens)
#define NTOK 4096
#define DDIM 1024
#define HDIM 4096
#define NEXP 8
#define NSLOT (NTOK * 2)

// ---------------- scratch (static device globals; no allocation) ------------
__device__ __half g_xhi[(size_t)NTOK * DDIM];
__device__ __half g_xlo[(size_t)NTOK * DDIM];
__device__ __half g_fchi[(size_t)NEXP * HDIM * DDIM];
__device__ __half g_pjhi[(size_t)NEXP * DDIM * HDIM];
__device__ __half g_hhi[(size_t)NSLOT * HDIM];
__device__ __half g_hlo[(size_t)NSLOT * HDIM];
__device__ float g_yp[(size_t)NSLOT * DDIM];
__device__ int   g_eidx[NSLOT];
__device__ float g_ew[NSLOT];
__device__ int   g_pos[NSLOT];
__device__ int   g_slotof[NSLOT];
__device__ int   g_perm[NSLOT];
__device__ int   g_cnt[NEXP];
__device__ int   g_base[NEXP];
__device__ float g_sump[NEXP];
__device__ float g_loss;

// ---------------- helpers ----------------------------------------------------
__device__ __forceinline__ uint32_t smem_u32(const void* p) {
    uint32_t a;
    asm("{ .reg .u64 t; cvta.to.shared.u64 t, %1; cvt.u32.u64 %0, t; }"
        : "=r"(a) : "l"(p));
    return a;
}

__device__ __forceinline__ uint32_t packh2(__half x, __half y) {
    __half2 h2 = __halves2half2(x, y);
    return *(uint32_t*)&h2;
}

// fp16 split: hi = rn(v), lo = rn(v - hi)
__device__ __forceinline__ void split2h(float x, float y, uint32_t& hi, uint32_t& lo) {
    __half hx = __float2half_rn(x), hy = __float2half_rn(y);
    hi = packh2(hx, hy);
    lo = packh2(__float2half_rn(x - __half2float(hx)),
                __float2half_rn(y - __half2float(hy)));
}

// ---------------- precision-split conversions --------------------------------
__global__ void convert_hl_kernel(const float* __restrict__ src,
                                  __half* __restrict__ hi,
                                  __half* __restrict__ lo, int n4) {
    int i = blockIdx.x * blockDim.x + threadIdx.x;
    int stride = gridDim.x * blockDim.x;
    for (; i < n4; i += stride) {
        float4 v = ((const float4*)src)[i];
        uint32_t h0, l0, h1, l1;
        split2h(v.x, v.y, h0, l0);
        split2h(v.z, v.w, h1, l1);
        ((uint2*)hi)[i] = make_uint2(h0, h1);
        ((uint2*)lo)[i] = make_uint2(l0, l1);
    }
}

__global__ void convert_hi_kernel(const float* __restrict__ src,
                                  __half* __restrict__ hi, int n4) {
    int i = blockIdx.x * blockDim.x + threadIdx.x;
    int stride = gridDim.x * blockDim.x;
    for (; i < n4; i += stride) {
        float4 v = ((const float4*)src)[i];
        uint32_t h0 = packh2(__float2half_rn(v.x), __float2half_rn(v.y));
        uint32_t h1 = packh2(__float2half_rn(v.z), __float2half_rn(v.w));
        ((uint2*)hi)[i] = make_uint2(h0, h1);
    }
}

// ---------------- init -------------------------------------------------------
__global__ void init_kernel() {
    int t = threadIdx.x;
    if (t < NEXP) { g_cnt[t] = 0; g_sump[t] = 0.0f; }
}

// ---------------- gating: 1 warp per token -----------------------------------
__global__ void gating_kernel(const float* __restrict__ x,
                              const float* __restrict__ wg) {
    int warp = (blockIdx.x * blockDim.x + threadIdx.x) >> 5;
    int lane = threadIdx.x & 31;
    if (warp >= NTOK) return;
    const float* xr = x + (size_t)warp * DDIM;

    float acc[NEXP];
#pragma unroll
    for (int e = 0; e < NEXP; e++) acc[e] = 0.0f;

    for (int d = lane; d < DDIM; d += 32) {
        float xv = xr[d];
#pragma unroll
        for (int e = 0; e < NEXP; e++) acc[e] += xv * wg[e * DDIM + d];
    }
#pragma unroll
    for (int e = 0; e < NEXP; e++) {
#pragma unroll
        for (int o = 16; o > 0; o >>= 1)
            acc[e] += __shfl_xor_sync(0xFFFFFFFFu, acc[e], o);
    }

    if (lane == 0) {
        float mx = acc[0];
#pragma unroll
        for (int e = 1; e < NEXP; e++) mx = fmaxf(mx, acc[e]);
        float p[NEXP], s = 0.0f;
#pragma unroll
        for (int e = 0; e < NEXP; e++) { p[e] = __expf(acc[e] - mx); s += p[e]; }
        float inv = 1.0f / s;
#pragma unroll
        for (int e = 0; e < NEXP; e++) p[e] *= inv;

#pragma unroll
        for (int e = 0; e < NEXP; e++) atomicAdd(&g_sump[e], p[e]);

        int i0 = 0;
#pragma unroll
        for (int e = 1; e < NEXP; e++) if (p[e] > p[i0]) i0 = e;
        int i1 = (i0 == 0) ? 1 : 0;
#pragma unroll
        for (int e = 0; e < NEXP; e++) if (e != i0 && p[e] > p[i1]) i1 = e;

        float w0 = p[i0], w1 = p[i1];
        float rinv = 1.0f / (w0 + w1);
        w0 *= rinv; w1 *= rinv;

        g_eidx[2 * warp + 0] = i0;
        g_eidx[2 * warp + 1] = i1;
        g_ew[2 * warp + 0] = w0;
        g_ew[2 * warp + 1] = w1;
        g_pos[2 * warp + 0] = atomicAdd(&g_cnt[i0], 1);
        g_pos[2 * warp + 1] = atomicAdd(&g_cnt[i1], 1);
    }
}

// ---------------- prefix + balance loss --------------------------------------
__global__ void prefix_kernel() {
    if (threadIdx.x == 0) {
        int b = 0;
        float loss = 0.0f;
        for (int e = 0; e < NEXP; e++) {
            g_base[e] = b;
            b += g_cnt[e];
            loss += g_sump[e] * (float)g_cnt[e];
        }
        g_loss = loss * (float)NEXP / ((float)NTOK * (float)NTOK);
    }
}

// ---------------- scatter ----------------------------------------------------
__global__ void scatter_kernel() {
    int t = blockIdx.x * blockDim.x + threadIdx.x;
    if (t < NSLOT) {
        int e = g_eidx[t];
        int slot = g_base[e] + g_pos[t];
        g_slotof[t] = slot;
        g_perm[slot] = t >> 1;
    }
}

// ---------------- fp16x2 mma.sync grouped GEMM, cp.async pipelined -----------
// D[m,n] = sum_k A[m,k]*B[n,k], A split hi/lo (fp16), B rounded to fp16 hi.
// acc += Ahi*Bhi + Alo*Bhi   (dropped A*Blo ~2^-12 relative).
// CTA tile 128x64, K chunk 32, 8 warps 4(M)x2(N), warp tile 32x32.
// Double-buffered SMEM via cp.async.
#define TM 128
#define TN 64
#define TKC 32
#define SROW 40                    // halves per smem row (80B, conflict-free)
#define A_HI 0
#define A_LO 10240                 // 128*80
#define B_HI 20480                 // +64*80 = 5120
#define SSTG 25600
#define SMEM_DYN (2 * SSTG)        // 51200

#define CPA16(dst, src, sz) \
    asm volatile("cp.async.cg.shared.global [%0], [%1], 16, %2;" \
                 :: "r"(dst), "l"(src), "r"(sz))
#define CPA_COMMIT() asm volatile("cp.async.commit_group;" ::: "memory")
#define CPA_WAIT1() asm volatile("cp.async.wait_group 1;" ::: "memory")
#define CPA_WAIT0() asm volatile("cp.async.wait_group 0;" ::: "memory")

#define LDSM4(r, addr) \
    asm volatile("ldmatrix.sync.aligned.m8n8.x4.shared.b16 {%0,%1,%2,%3}, [%4];" \
                 : "=r"((r)[0]), "=r"((r)[1]), "=r"((r)[2]), "=r"((r)[3]) \
                 : "r"(addr))

#define MMAF16(c, a, b0_, b1_) \
    asm volatile("mma.sync.aligned.m16n8k16.row.col.f32.f16.f16.f32 " \
                 "{%0,%1,%2,%3}, {%4,%5,%6,%7}, {%8,%9}, {%0,%1,%2,%3};" \
                 : "+f"((c)[0]), "+f"((c)[1]), "+f"((c)[2]), "+f"((c)[3]) \
                 : "r"((a)[0]), "r"((a)[1]), "r"((a)[2]), "r"((a)[3]), \
                   "r"(b0_), "r"(b1_))

template <int KD, int ND, bool PH1>
__global__ __launch_bounds__(256)
void gemm_f16(const __half* __restrict__ Ahi_,
              const __half* __restrict__ Alo_,
              const __half* __restrict__ Bhi_) {
    extern __shared__ __align__(16) unsigned char smem[];
    int e = blockIdx.z;
    int count = g_cnt[e];
    int m0 = blockIdx.y * TM;
    if (m0 >= count) return;
    int n0 = blockIdx.x * TN;
    int base = g_base[e];

    const __half* Bhi = Bhi_ + (size_t)e * KD * ND;

    int tid = threadIdx.x;
    int lane = tid & 31;
    int wid = tid >> 5;
    int warp_m = wid & 3;
    int warp_n = wid >> 2;
    uint32_t sb = smem_u32(smem);

    // --- cp.async loader mapping ---
    int arow = tid >> 1;                 // A tile row 0..127
    int ahalf = tid & 1;                 // which 32B half of the 64B row
    int browi = tid >> 2;                // B tile row 0..63
    int bq = tid & 3;                    // 16B unit 0..3

    int am = m0 + arow;
    bool av = am < count;
    int gidx = 0;
    if (av) gidx = PH1 ? g_perm[base + am] : (base + am);
    uint32_t asz = av ? 16u : 0u;
    const __half* a_hi_src = Ahi_ + (size_t)gidx * KD + ahalf * 16;
    const __half* a_lo_src = Alo_ + (size_t)gidx * KD + ahalf * 16;
    const __half* b_hi_src = Bhi + (size_t)(n0 + browi) * KD + bq * 8;

    uint32_t a_dst = sb + arow * (SROW * 2) + ahalf * 32;
    uint32_t b_dst = sb + browi * (SROW * 2) + bq * 16;

    // --- ldmatrix lane addresses (relative to stage base) ---
    uint32_t arow_l = (uint32_t)(warp_m * 32 + (lane & 7) + ((lane >> 3) & 1) * 8);
    uint32_t akoff = (uint32_t)((lane >> 4) * 8);
    uint32_t a_ld = sb + (arow_l * SROW + akoff) * 2;
    uint32_t brow_l = (uint32_t)(warp_n * 32 + (lane & 7) + (lane >> 4) * 8);
    uint32_t bkoff = (uint32_t)(((lane >> 3) & 1) * 8);
    uint32_t b_ld = sb + B_HI + (brow_l * SROW + bkoff) * 2;

    float acc[2][4][4];
#pragma unroll
    for (int i = 0; i < 2; i++)
#pragma unroll
        for (int j = 0; j < 4; j++)
#pragma unroll
            for (int q = 0; q < 4; q++) acc[i][j][q] = 0.0f;

    auto issue = [&](int s, int k0) {
        uint32_t ad = a_dst + s * SSTG;
        CPA16(ad + A_HI,      a_hi_src + k0,     asz);
        CPA16(ad + A_HI + 16, a_hi_src + k0 + 8, asz);
        CPA16(ad + A_LO,      a_lo_src + k0,     asz);
        CPA16(ad + A_LO + 16, a_lo_src + k0 + 8, asz);
        CPA16(b_dst + s * SSTG + B_HI, b_hi_src + k0, 16u);
    };

    const int NCH = KD / TKC;
    issue(0, 0);
    CPA_COMMIT();

    for (int c = 0; c < NCH; c++) {
        if (c + 1 < NCH) {
            issue((c + 1) & 1, (c + 1) * TKC);
            CPA_COMMIT();
            CPA_WAIT1();
        } else {
            CPA_WAIT0();
        }
        __syncthreads();

        int s = c & 1;
        uint32_t abase = a_ld + s * SSTG;
        uint32_t bbase = b_ld + s * SSTG;
#pragma unroll
        for (int ks = 0; ks < 2; ks++) {
            uint32_t ah0[4], ah1[4], al0[4], al1[4];
            uint32_t aad = abase + ks * 32;
            LDSM4(ah0, aad);
            LDSM4(ah1, aad + 16 * SROW * 2);
            LDSM4(al0, aad + A_LO);
            LDSM4(al1, aad + A_LO + 16 * SROW * 2);
#pragma unroll
            for (int np = 0; np < 2; np++) {
                uint32_t bh[4];
                LDSM4(bh, bbase + ks * 32 + np * 16 * SROW * 2);

                MMAF16(acc[0][np * 2 + 0], ah0, bh[0], bh[1]);
                MMAF16(acc[0][np * 2 + 0], al0, bh[0], bh[1]);
                MMAF16(acc[0][np * 2 + 1], ah0, bh[2], bh[3]);
                MMAF16(acc[0][np * 2 + 1], al0, bh[2], bh[3]);

                MMAF16(acc[1][np * 2 + 0], ah1, bh[0], bh[1]);
                MMAF16(acc[1][np * 2 + 0], al1, bh[0], bh[1]);
                MMAF16(acc[1][np * 2 + 1], ah1, bh[2], bh[3]);
                MMAF16(acc[1][np * 2 + 1], al1, bh[2], bh[3]);
            }
        }
        __syncthreads();
    }

    // epilogue
    int g = lane >> 2, t4 = lane & 3;
#pragma unroll
    for (int mt = 0; mt < 2; mt++) {
        int mr = m0 + warp_m * 32 + mt * 16 + g;
#pragma unroll
        for (int nt = 0; nt < 4; nt++) {
            int col = n0 + warp_n * 32 + nt * 8 + 2 * t4;
            float2 v0, v1;
            v0.x = acc[mt][nt][0]; v0.y = acc[mt][nt][1];
            v1.x = acc[mt][nt][2]; v1.y = acc[mt][nt][3];
            if (PH1) {
                v0.x = fmaxf(v0.x, 0.f); v0.x *= v0.x;
                v0.y = fmaxf(v0.y, 0.f); v0.y *= v0.y;
                v1.x = fmaxf(v1.x, 0.f); v1.x *= v1.x;
                v1.y = fmaxf(v1.y, 0.f); v1.y *= v1.y;
                uint32_t h, l;
                if (mr < count) {
                    size_t o = (size_t)(base + mr) * ND + col;
                    split2h(v0.x, v0.y, h, l);
                    *(uint32_t*)(g_hhi + o) = h;
                    *(uint32_t*)(g_hlo + o) = l;
                }
                if (mr + 8 < count) {
                    size_t o = (size_t)(base + mr + 8) * ND + col;
                    split2h(v1.x, v1.y, h, l);
                    *(uint32_t*)(g_hhi + o) = h;
                    *(uint32_t*)(g_hlo + o) = l;
                }
            } else {
                if (mr < count)
                    *(float2*)(g_yp + (size_t)(base + mr) * ND + col) = v0;
                if (mr + 8 < count)
                    *(float2*)(g_yp + (size_t)(base + mr + 8) * ND + col) = v1;
            }
        }
    }
}

// ---------------- combine ----------------------------------------------------
__global__ void combine_kernel(float* __restrict__ out, int out_size) {
    const int nv = DDIM / 4;
    int t = blockIdx.x * blockDim.x + threadIdx.x;
    if (t < NTOK * nv) {
        int n = t / nv, dv = t % nv;
        int s0 = g_slotof[2 * n], s1 = g_slotof[2 * n + 1];
        float w0 = g_ew[2 * n], w1 = g_ew[2 * n + 1];
        const float4* yp = (const float4*)g_yp;
        float4 a = yp[(size_t)s0 * nv + dv];
        float4 b = yp[(size_t)s1 * nv + dv];
        float4 r;
        r.x = w0 * a.x + w1 * b.x;
        r.y = w0 * a.y + w1 * b.y;
        r.z = w0 * a.z + w1 * b.z;
        r.w = w0 * a.w + w1 * b.w;
        ((float4*)out)[t] = r;
    }
    if (t == 0) {
        for (int idx = NTOK * DDIM; idx < out_size; idx++) out[idx] = g_loss;
    }
}

// ---------------- launch -----------------------------------------------------
extern "C" void kernel_launch(void* const* d_in, const int* in_sizes, int n_in,
                              void* d_out, int out_size) {
    const float* x   = (const float*)d_in[0];
    const float* wg  = (const float*)d_in[1];
    const float* wfc = (const float*)d_in[2];
    const float* wpj = (const float*)d_in[3];
    float* out = (float*)d_out;

    cudaFuncSetAttribute(gemm_f16<DDIM, HDIM, true>,
                         cudaFuncAttributeMaxDynamicSharedMemorySize, SMEM_DYN);
    cudaFuncSetAttribute(gemm_f16<HDIM, DDIM, false>,
                         cudaFuncAttributeMaxDynamicSharedMemorySize, SMEM_DYN);

    __half *xhi, *xlo, *fchi, *pjhi, *hhi, *hlo;
    cudaGetSymbolAddress((void**)&xhi, g_xhi);
    cudaGetSymbolAddress((void**)&xlo, g_xlo);
    cudaGetSymbolAddress((void**)&fchi, g_fchi);
    cudaGetSymbolAddress((void**)&pjhi, g_pjhi);
    cudaGetSymbolAddress((void**)&hhi, g_hhi);
    cudaGetSymbolAddress((void**)&hlo, g_hlo);

    init_kernel<<<1, 32>>>();
    convert_hl_kernel<<<1184, 256>>>(x, xhi, xlo, NTOK * DDIM / 4);
    convert_hi_kernel<<<1184, 256>>>(wfc, fchi, NEXP * HDIM * DDIM / 4);
    convert_hi_kernel<<<1184, 256>>>(wpj, pjhi, NEXP * DDIM * HDIM / 4);
    gating_kernel<<<NTOK / 4, 128>>>(x, wg);
    prefix_kernel<<<1, 32>>>();
    scatter_kernel<<<(NSLOT + 255) / 256, 256>>>();

    dim3 g1(HDIM / TN, NSLOT / TM, NEXP);   // 64 x 64 x 8
    gemm_f16<DDIM, HDIM, true><<<g1, 256, SMEM_DYN>>>(xhi, xlo, fchi);

    dim3 g2(DDIM / TN, NSLOT / TM, NEXP);   // 16 x 64 x 8
    gemm_f16<HDIM, DDIM, false><<<g2, 256, SMEM_DYN>>>(hhi, hlo, pjhi);

    combine_kernel<<<(NTOK * DDIM / 4 + 255) / 256, 256>>>(out, out_size);
}

// round 13
// speedup vs baseline: 2.3516x; 1.2680x over previous
#include <cuda_runtime.h>
#include <cuda_fp16.h>
#include <cstdint>

// Problem constants (B=2, T=2048 -> N=4096 tokens)
#define NTOK 4096
#define DDIM 1024
#define HDIM 4096
#define NEXP 8
#define NSLOT (NTOK * 2)

// ---------------- scratch (static device globals; no allocation) ------------
__device__ __half g_xhi[(size_t)NTOK * DDIM];
__device__ __half g_xlo[(size_t)NTOK * DDIM];
__device__ __half g_fchi[(size_t)NEXP * HDIM * DDIM];
__device__ __half g_pjhi[(size_t)NEXP * DDIM * HDIM];
__device__ __half g_hhi[(size_t)NSLOT * HDIM];
__device__ float g_yp[(size_t)NSLOT * DDIM];
__device__ int   g_eidx[NSLOT];
__device__ float g_ew[NSLOT];
__device__ int   g_pos[NSLOT];
__device__ int   g_slotof[NSLOT];
__device__ int   g_perm[NSLOT];
__device__ int   g_cnt[NEXP];
__device__ int   g_base[NEXP];
__device__ float g_sump[NEXP];
__device__ float g_loss;

// ---------------- helpers ----------------------------------------------------
__device__ __forceinline__ uint32_t smem_u32(const void* p) {
    uint32_t a;
    asm("{ .reg .u64 t; cvta.to.shared.u64 t, %1; cvt.u32.u64 %0, t; }"
        : "=r"(a) : "l"(p));
    return a;
}

__device__ __forceinline__ uint32_t packh2(__half x, __half y) {
    __half2 h2 = __halves2half2(x, y);
    return *(uint32_t*)&h2;
}

// fp16 split: hi = rn(v), lo = rn(v - hi)
__device__ __forceinline__ void split2h(float x, float y, uint32_t& hi, uint32_t& lo) {
    __half hx = __float2half_rn(x), hy = __float2half_rn(y);
    hi = packh2(hx, hy);
    lo = packh2(__float2half_rn(x - __half2float(hx)),
                __float2half_rn(y - __half2float(hy)));
}

// ---------------- precision-split conversions --------------------------------
__global__ void convert_hl_kernel(const float* __restrict__ src,
                                  __half* __restrict__ hi,
                                  __half* __restrict__ lo, int n4) {
    int i = blockIdx.x * blockDim.x + threadIdx.x;
    int stride = gridDim.x * blockDim.x;
    for (; i < n4; i += stride) {
        float4 v = ((const float4*)src)[i];
        uint32_t h0, l0, h1, l1;
        split2h(v.x, v.y, h0, l0);
        split2h(v.z, v.w, h1, l1);
        ((uint2*)hi)[i] = make_uint2(h0, h1);
        ((uint2*)lo)[i] = make_uint2(l0, l1);
    }
}

__global__ void convert_hi_kernel(const float* __restrict__ src,
                                  __half* __restrict__ hi, int n4) {
    int i = blockIdx.x * blockDim.x + threadIdx.x;
    int stride = gridDim.x * blockDim.x;
    for (; i < n4; i += stride) {
        float4 v = ((const float4*)src)[i];
        uint32_t h0 = packh2(__float2half_rn(v.x), __float2half_rn(v.y));
        uint32_t h1 = packh2(__float2half_rn(v.z), __float2half_rn(v.w));
        ((uint2*)hi)[i] = make_uint2(h0, h1);
    }
}

// ---------------- init -------------------------------------------------------
__global__ void init_kernel() {
    int t = threadIdx.x;
    if (t < NEXP) { g_cnt[t] = 0; g_sump[t] = 0.0f; }
}

// ---------------- gating: 1 warp per token -----------------------------------
__global__ void gating_kernel(const float* __restrict__ x,
                              const float* __restrict__ wg) {
    int warp = (blockIdx.x * blockDim.x + threadIdx.x) >> 5;
    int lane = threadIdx.x & 31;
    if (warp >= NTOK) return;
    const float* xr = x + (size_t)warp * DDIM;

    float acc[NEXP];
#pragma unroll
    for (int e = 0; e < NEXP; e++) acc[e] = 0.0f;

    for (int d = lane; d < DDIM; d += 32) {
        float xv = xr[d];
#pragma unroll
        for (int e = 0; e < NEXP; e++) acc[e] += xv * wg[e * DDIM + d];
    }
#pragma unroll
    for (int e = 0; e < NEXP; e++) {
#pragma unroll
        for (int o = 16; o > 0; o >>= 1)
            acc[e] += __shfl_xor_sync(0xFFFFFFFFu, acc[e], o);
    }

    if (lane == 0) {
        float mx = acc[0];
#pragma unroll
        for (int e = 1; e < NEXP; e++) mx = fmaxf(mx, acc[e]);
        float p[NEXP], s = 0.0f;
#pragma unroll
        for (int e = 0; e < NEXP; e++) { p[e] = __expf(acc[e] - mx); s += p[e]; }
        float inv = 1.0f / s;
#pragma unroll
        for (int e = 0; e < NEXP; e++) p[e] *= inv;

#pragma unroll
        for (int e = 0; e < NEXP; e++) atomicAdd(&g_sump[e], p[e]);

        int i0 = 0;
#pragma unroll
        for (int e = 1; e < NEXP; e++) if (p[e] > p[i0]) i0 = e;
        int i1 = (i0 == 0) ? 1 : 0;
#pragma unroll
        for (int e = 0; e < NEXP; e++) if (e != i0 && p[e] > p[i1]) i1 = e;

        float w0 = p[i0], w1 = p[i1];
        float rinv = 1.0f / (w0 + w1);
        w0 *= rinv; w1 *= rinv;

        g_eidx[2 * warp + 0] = i0;
        g_eidx[2 * warp + 1] = i1;
        g_ew[2 * warp + 0] = w0;
        g_ew[2 * warp + 1] = w1;
        g_pos[2 * warp + 0] = atomicAdd(&g_cnt[i0], 1);
        g_pos[2 * warp + 1] = atomicAdd(&g_cnt[i1], 1);
    }
}

// ---------------- prefix + balance loss --------------------------------------
__global__ void prefix_kernel() {
    if (threadIdx.x == 0) {
        int b = 0;
        float loss = 0.0f;
        for (int e = 0; e < NEXP; e++) {
            g_base[e] = b;
            b += g_cnt[e];
            loss += g_sump[e] * (float)g_cnt[e];
        }
        g_loss = loss * (float)NEXP / ((float)NTOK * (float)NTOK);
    }
}

// ---------------- scatter ----------------------------------------------------
__global__ void scatter_kernel() {
    int t = blockIdx.x * blockDim.x + threadIdx.x;
    if (t < NSLOT) {
        int e = g_eidx[t];
        int slot = g_base[e] + g_pos[t];
        g_slotof[t] = slot;
        g_perm[slot] = t >> 1;
    }
}

// ---------------- fp16 mma.sync grouped GEMM, 3-stage cp.async pipeline ------
// D[m,n] = sum_k A[m,k]*B[n,k], B rounded to fp16.
// ALO=true : acc += Ahi*Bhi + Alo*Bhi  (A split hi/lo)
// ALO=false: acc += Ahi*Bhi            (A plain fp16)
// CTA tile 128x64, K chunk 32, 8 warps 4(M)x2(N), warp tile 32x32.
// 3-stage SMEM pipeline, ONE __syncthreads per chunk.
#define TM 128
#define TN 64
#define TKC 32
#define SROW 40                    // halves per smem row (80B, conflict-free)
#define A_LO_OFF 10240             // 128*80

#define CPA16(dst, src, sz) \
    asm volatile("cp.async.cg.shared.global [%0], [%1], 16, %2;" \
                 :: "r"(dst), "l"(src), "r"(sz))
#define CPA_COMMIT() asm volatile("cp.async.commit_group;" ::: "memory")
#define CPA_WAIT1() asm volatile("cp.async.wait_group 1;" ::: "memory")
#define CPA_WAIT0() asm volatile("cp.async.wait_group 0;" ::: "memory")

#define LDSM4(r, addr) \
    asm volatile("ldmatrix.sync.aligned.m8n8.x4.shared.b16 {%0,%1,%2,%3}, [%4];" \
                 : "=r"((r)[0]), "=r"((r)[1]), "=r"((r)[2]), "=r"((r)[3]) \
                 : "r"(addr))

#define MMAF16(c, a, b0_, b1_) \
    asm volatile("mma.sync.aligned.m16n8k16.row.col.f32.f16.f16.f32 " \
                 "{%0,%1,%2,%3}, {%4,%5,%6,%7}, {%8,%9}, {%0,%1,%2,%3};" \
                 : "+f"((c)[0]), "+f"((c)[1]), "+f"((c)[2]), "+f"((c)[3]) \
                 : "r"((a)[0]), "r"((a)[1]), "r"((a)[2]), "r"((a)[3]), \
                   "r"(b0_), "r"(b1_))

template <int KD, int ND, bool PH1, bool ALO>
__global__ __launch_bounds__(256)
void gemm_f16(const __half* __restrict__ Ahi_,
              const __half* __restrict__ Alo_,
              const __half* __restrict__ Bhi_) {
    constexpr int B_OFF = ALO ? 20480 : 10240;   // after A tiles
    constexpr int SSTG = B_OFF + 5120;           // + B tile (64*80)

    extern __shared__ __align__(16) unsigned char smem[];
    int e = blockIdx.z;
    int count = g_cnt[e];
    int m0 = blockIdx.y * TM;
    if (m0 >= count) return;
    int n0 = blockIdx.x * TN;
    int base = g_base[e];

    const __half* Bhi = Bhi_ + (size_t)e * KD * ND;

    int tid = threadIdx.x;
    int lane = tid & 31;
    int wid = tid >> 5;
    int warp_m = wid & 3;
    int warp_n = wid >> 2;
    uint32_t sb = smem_u32(smem);

    // --- cp.async loader mapping ---
    int arow = tid >> 1;                 // A tile row 0..127
    int ahalf = tid & 1;                 // which 32B half of the 64B row
    int browi = tid >> 2;                // B tile row 0..63
    int bq = tid & 3;                    // 16B unit 0..3

    int am = m0 + arow;
    bool av = am < count;
    int gidx = 0;
    if (av) gidx = PH1 ? g_perm[base + am] : (base + am);
    uint32_t asz = av ? 16u : 0u;
    const __half* a_hi_src = Ahi_ + (size_t)gidx * KD + ahalf * 16;
    const __half* a_lo_src = Alo_ + (size_t)gidx * KD + ahalf * 16;
    const __half* b_hi_src = Bhi + (size_t)(n0 + browi) * KD + bq * 8;

    uint32_t a_dst = sb + arow * (SROW * 2) + ahalf * 32;
    uint32_t b_dst = sb + browi * (SROW * 2) + bq * 16;

    // --- ldmatrix lane addresses (relative to stage base) ---
    uint32_t arow_l = (uint32_t)(warp_m * 32 + (lane & 7) + ((lane >> 3) & 1) * 8);
    uint32_t akoff = (uint32_t)((lane >> 4) * 8);
    uint32_t a_ld = sb + (arow_l * SROW + akoff) * 2;
    uint32_t brow_l = (uint32_t)(warp_n * 32 + (lane & 7) + (lane >> 4) * 8);
    uint32_t bkoff = (uint32_t)(((lane >> 3) & 1) * 8);
    uint32_t b_ld = sb + B_OFF + (brow_l * SROW + bkoff) * 2;

    float acc[2][4][4];
#pragma unroll
    for (int i = 0; i < 2; i++)
#pragma unroll
        for (int j = 0; j < 4; j++)
#pragma unroll
            for (int q = 0; q < 4; q++) acc[i][j][q] = 0.0f;

    auto issue = [&](int s, int k0) {
        uint32_t ad = a_dst + s * SSTG;
        CPA16(ad,      a_hi_src + k0,     asz);
        CPA16(ad + 16, a_hi_src + k0 + 8, asz);
        if (ALO) {
            CPA16(ad + A_LO_OFF,      a_lo_src + k0,     asz);
            CPA16(ad + A_LO_OFF + 16, a_lo_src + k0 + 8, asz);
        }
        CPA16(b_dst + s * SSTG + B_OFF, b_hi_src + k0, 16u);
    };

    const int NCH = KD / TKC;
    issue(0, 0);
    CPA_COMMIT();
    issue(1, TKC);
    CPA_COMMIT();

    int s = 0;
    for (int c = 0; c < NCH; c++) {
        if (c < NCH - 1) CPA_WAIT1(); else CPA_WAIT0();
        __syncthreads();
        if (c + 2 < NCH) {
            int ns = s + 2; if (ns >= 3) ns -= 3;
            issue(ns, (c + 2) * TKC);
            CPA_COMMIT();
        }

        uint32_t abase = a_ld + s * SSTG;
        uint32_t bbase = b_ld + s * SSTG;
#pragma unroll
        for (int ks = 0; ks < 2; ks++) {
            uint32_t ah0[4], ah1[4], al0[4], al1[4];
            uint32_t aad = abase + ks * 32;
            LDSM4(ah0, aad);
            LDSM4(ah1, aad + 16 * SROW * 2);
            if (ALO) {
                LDSM4(al0, aad + A_LO_OFF);
                LDSM4(al1, aad + A_LO_OFF + 16 * SROW * 2);
            }
#pragma unroll
            for (int np = 0; np < 2; np++) {
                uint32_t bh[4];
                LDSM4(bh, bbase + ks * 32 + np * 16 * SROW * 2);

                MMAF16(acc[0][np * 2 + 0], ah0, bh[0], bh[1]);
                MMAF16(acc[0][np * 2 + 1], ah0, bh[2], bh[3]);
                MMAF16(acc[1][np * 2 + 0], ah1, bh[0], bh[1]);
                MMAF16(acc[1][np * 2 + 1], ah1, bh[2], bh[3]);
                if (ALO) {
                    MMAF16(acc[0][np * 2 + 0], al0, bh[0], bh[1]);
                    MMAF16(acc[0][np * 2 + 1], al0, bh[2], bh[3]);
                    MMAF16(acc[1][np * 2 + 0], al1, bh[0], bh[1]);
                    MMAF16(acc[1][np * 2 + 1], al1, bh[2], bh[3]);
                }
            }
        }
        if (++s >= 3) s = 0;
    }

    // epilogue
    int g = lane >> 2, t4 = lane & 3;
#pragma unroll
    for (int mt = 0; mt < 2; mt++) {
        int mr = m0 + warp_m * 32 + mt * 16 + g;
#pragma unroll
        for (int nt = 0; nt < 4; nt++) {
            int col = n0 + warp_n * 32 + nt * 8 + 2 * t4;
            float2 v0, v1;
            v0.x = acc[mt][nt][0]; v0.y = acc[mt][nt][1];
            v1.x = acc[mt][nt][2]; v1.y = acc[mt][nt][3];
            if (PH1) {
                v0.x = fmaxf(v0.x, 0.f); v0.x *= v0.x;
                v0.y = fmaxf(v0.y, 0.f); v0.y *= v0.y;
                v1.x = fmaxf(v1.x, 0.f); v1.x *= v1.x;
                v1.y = fmaxf(v1.y, 0.f); v1.y *= v1.y;
                if (mr < count) {
                    size_t o = (size_t)(base + mr) * ND + col;
                    *(uint32_t*)(g_hhi + o) =
                        packh2(__float2half_rn(v0.x), __float2half_rn(v0.y));
                }
                if (mr + 8 < count) {
                    size_t o = (size_t)(base + mr + 8) * ND + col;
                    *(uint32_t*)(g_hhi + o) =
                        packh2(__float2half_rn(v1.x), __float2half_rn(v1.y));
                }
            } else {
                if (mr < count)
                    *(float2*)(g_yp + (size_t)(base + mr) * ND + col) = v0;
                if (mr + 8 < count)
                    *(float2*)(g_yp + (size_t)(base + mr + 8) * ND + col) = v1;
            }
        }
    }
}

// ---------------- combine ----------------------------------------------------
__global__ void combine_kernel(float* __restrict__ out, int out_size) {
    const int nv = DDIM / 4;
    int t = blockIdx.x * blockDim.x + threadIdx.x;
    if (t < NTOK * nv) {
        int n = t / nv, dv = t % nv;
        int s0 = g_slotof[2 * n], s1 = g_slotof[2 * n + 1];
        float w0 = g_ew[2 * n], w1 = g_ew[2 * n + 1];
        const float4* yp = (const float4*)g_yp;
        float4 a = yp[(size_t)s0 * nv + dv];
        float4 b = yp[(size_t)s1 * nv + dv];
        float4 r;
        r.x = w0 * a.x + w1 * b.x;
        r.y = w0 * a.y + w1 * b.y;
        r.z = w0 * a.z + w1 * b.z;
        r.w = w0 * a.w + w1 * b.w;
        ((float4*)out)[t] = r;
    }
    if (t == 0) {
        for (int idx = NTOK * DDIM; idx < out_size; idx++) out[idx] = g_loss;
    }
}

// ---------------- launch -----------------------------------------------------
extern "C" void kernel_launch(void* const* d_in, const int* in_sizes, int n_in,
                              void* d_out, int out_size) {
    const float* x   = (const float*)d_in[0];
    const float* wg  = (const float*)d_in[1];
    const float* wfc = (const float*)d_in[2];
    const float* wpj = (const float*)d_in[3];
    float* out = (float*)d_out;

    const int smem1 = 3 * (20480 + 5120);   // 76800
    const int smem2 = 3 * (10240 + 5120);   // 46080
    cudaFuncSetAttribute(gemm_f16<DDIM, HDIM, true, true>,
                         cudaFuncAttributeMaxDynamicSharedMemorySize, smem1);
    cudaFuncSetAttribute(gemm_f16<HDIM, DDIM, false, false>,
                         cudaFuncAttributeMaxDynamicSharedMemorySize, smem2);

    __half *xhi, *xlo, *fchi, *pjhi, *hhi;
    cudaGetSymbolAddress((void**)&xhi, g_xhi);
    cudaGetSymbolAddress((void**)&xlo, g_xlo);
    cudaGetSymbolAddress((void**)&fchi, g_fchi);
    cudaGetSymbolAddress((void**)&pjhi, g_pjhi);
    cudaGetSymbolAddress((void**)&hhi, g_hhi);

    init_kernel<<<1, 32>>>();
    convert_hl_kernel<<<1184, 256>>>(x, xhi, xlo, NTOK * DDIM / 4);
    convert_hi_kernel<<<1184, 256>>>(wfc, fchi, NEXP * HDIM * DDIM / 4);
    convert_hi_kernel<<<1184, 256>>>(wpj, pjhi, NEXP * DDIM * HDIM / 4);
    gating_kernel<<<NTOK / 4, 128>>>(x, wg);
    prefix_kernel<<<1, 32>>>();
    scatter_kernel<<<(NSLOT + 255) / 256, 256>>>();

    dim3 g1(HDIM / TN, NSLOT / TM, NEXP);   // 64 x 64 x 8
    gemm_f16<DDIM, HDIM, true, true><<<g1, 256, smem1>>>(xhi, xlo, fchi);

    dim3 g2(DDIM / TN, NSLOT / TM, NEXP);   // 16 x 64 x 8
    gemm_f16<HDIM, DDIM, false, false><<<g2, 256, smem2>>>(hhi, hhi, pjhi);

    combine_kernel<<<(NTOK * DDIM / 4 + 255) / 256, 256>>>(out, out_size);
}

// round 15
// speedup vs baseline: 2.7984x; 1.1900x over previous
#include <cuda_runtime.h>
#include <cuda_fp16.h>
#include <cstdint>

// Problem constants (B=2, T=2048 -> N=4096 tokens)
#define NTOK 4096
#define DDIM 1024
#define HDIM 4096
#define NEXP 8
#define NSLOT (NTOK * 2)

// ---------------- scratch (static device globals; no allocation) ------------
__device__ __half g_xhi[(size_t)NTOK * DDIM];
__device__ __half g_xlo[(size_t)NTOK * DDIM];
__device__ __half g_fchi[(size_t)NEXP * HDIM * DDIM];
__device__ __half g_pjhi[(size_t)NEXP * DDIM * HDIM];
__device__ __half g_hhi[(size_t)NSLOT * HDIM];
__device__ float g_yp[(size_t)NSLOT * DDIM];
__device__ int   g_eidx[NSLOT];
__device__ float g_ew[NSLOT];
__device__ int   g_pos[NSLOT];
__device__ int   g_slotof[NSLOT];
__device__ int   g_perm[NSLOT];
__device__ int   g_cnt[NEXP];
__device__ int   g_base[NEXP];
__device__ float g_sump[NEXP];
__device__ float g_loss;

// ---------------- helpers ----------------------------------------------------
__device__ __forceinline__ uint32_t smem_u32(const void* p) {
    uint32_t a;
    asm("{ .reg .u64 t; cvta.to.shared.u64 t, %1; cvt.u32.u64 %0, t; }"
        : "=r"(a) : "l"(p));
    return a;
}

__device__ __forceinline__ uint32_t packh2(__half x, __half y) {
    __half2 h2 = __halves2half2(x, y);
    return *(uint32_t*)&h2;
}

// fp16 split: hi = rn(v), lo = rn(v - hi)
__device__ __forceinline__ void split2h(float x, float y, uint32_t& hi, uint32_t& lo) {
    __half hx = __float2half_rn(x), hy = __float2half_rn(y);
    hi = packh2(hx, hy);
    lo = packh2(__float2half_rn(x - __half2float(hx)),
                __float2half_rn(y - __half2float(hy)));
}

// ---------------- precision-split conversions --------------------------------
__global__ void convert_hl_kernel(const float* __restrict__ src,
                                  __half* __restrict__ hi,
                                  __half* __restrict__ lo, int n4) {
    int i = blockIdx.x * blockDim.x + threadIdx.x;
    int stride = gridDim.x * blockDim.x;
    for (; i < n4; i += stride) {
        float4 v = ((const float4*)src)[i];
        uint32_t h0, l0, h1, l1;
        split2h(v.x, v.y, h0, l0);
        split2h(v.z, v.w, h1, l1);
        ((uint2*)hi)[i] = make_uint2(h0, h1);
        ((uint2*)lo)[i] = make_uint2(l0, l1);
    }
}

__global__ void convert_hi_kernel(const float* __restrict__ src,
                                  __half* __restrict__ hi, int n4) {
    int i = blockIdx.x * blockDim.x + threadIdx.x;
    int stride = gridDim.x * blockDim.x;
    for (; i < n4; i += stride) {
        float4 v = ((const float4*)src)[i];
        uint32_t h0 = packh2(__float2half_rn(v.x), __float2half_rn(v.y));
        uint32_t h1 = packh2(__float2half_rn(v.z), __float2half_rn(v.w));
        ((uint2*)hi)[i] = make_uint2(h0, h1);
    }
}

// ---------------- init -------------------------------------------------------
__global__ void init_kernel() {
    int t = threadIdx.x;
    if (t < NEXP) { g_cnt[t] = 0; g_sump[t] = 0.0f; }
}

// ---------------- gating: 1 warp per token -----------------------------------
__global__ void gating_kernel(const float* __restrict__ x,
                              const float* __restrict__ wg) {
    int warp = (blockIdx.x * blockDim.x + threadIdx.x) >> 5;
    int lane = threadIdx.x & 31;
    if (warp >= NTOK) return;
    const float* xr = x + (size_t)warp * DDIM;

    float acc[NEXP];
#pragma unroll
    for (int e = 0; e < NEXP; e++) acc[e] = 0.0f;

    for (int d = lane; d < DDIM; d += 32) {
        float xv = xr[d];
#pragma unroll
        for (int e = 0; e < NEXP; e++) acc[e] += xv * wg[e * DDIM + d];
    }
#pragma unroll
    for (int e = 0; e < NEXP; e++) {
#pragma unroll
        for (int o = 16; o > 0; o >>= 1)
            acc[e] += __shfl_xor_sync(0xFFFFFFFFu, acc[e], o);
    }

    if (lane == 0) {
        float mx = acc[0];
#pragma unroll
        for (int e = 1; e < NEXP; e++) mx = fmaxf(mx, acc[e]);
        float p[NEXP], s = 0.0f;
#pragma unroll
        for (int e = 0; e < NEXP; e++) { p[e] = __expf(acc[e] - mx); s += p[e]; }
        float inv = 1.0f / s;
#pragma unroll
        for (int e = 0; e < NEXP; e++) p[e] *= inv;

#pragma unroll
        for (int e = 0; e < NEXP; e++) atomicAdd(&g_sump[e], p[e]);

        int i0 = 0;
#pragma unroll
        for (int e = 1; e < NEXP; e++) if (p[e] > p[i0]) i0 = e;
        int i1 = (i0 == 0) ? 1 : 0;
#pragma unroll
        for (int e = 0; e < NEXP; e++) if (e != i0 && p[e] > p[i1]) i1 = e;

        float w0 = p[i0], w1 = p[i1];
        float rinv = 1.0f / (w0 + w1);
        w0 *= rinv; w1 *= rinv;

        g_eidx[2 * warp + 0] = i0;
        g_eidx[2 * warp + 1] = i1;
        g_ew[2 * warp + 0] = w0;
        g_ew[2 * warp + 1] = w1;
        g_pos[2 * warp + 0] = atomicAdd(&g_cnt[i0], 1);
        g_pos[2 * warp + 1] = atomicAdd(&g_cnt[i1], 1);
    }
}

// ---------------- prefix + balance loss --------------------------------------
__global__ void prefix_kernel() {
    if (threadIdx.x == 0) {
        int b = 0;
        float loss = 0.0f;
        for (int e = 0; e < NEXP; e++) {
            g_base[e] = b;
            b += g_cnt[e];
            loss += g_sump[e] * (float)g_cnt[e];
        }
        g_loss = loss * (float)NEXP / ((float)NTOK * (float)NTOK);
    }
}

// ---------------- scatter ----------------------------------------------------
__global__ void scatter_kernel() {
    int t = blockIdx.x * blockDim.x + threadIdx.x;
    if (t < NSLOT) {
        int e = g_eidx[t];
        int slot = g_base[e] + g_pos[t];
        g_slotof[t] = slot;
        g_perm[slot] = t >> 1;
    }
}

// ---------------- fp16 mma.sync grouped GEMM, 3-stage cp.async pipeline ------
// D[m,n] = sum_k A[m,k]*B[n,k], B rounded to fp16.
// ALO=true : acc += Ahi*Bhi + Alo*Bhi  (A split hi/lo)
// ALO=false: acc += Ahi*Bhi            (A plain fp16)
// CTA tile 128x128, K chunk 32, 8 warps 4(M)x2(N), warp tile 32x64.
// 3-stage SMEM pipeline, ONE __syncthreads per chunk.
#define TM 128
#define TN 128
#define TKC 32
#define SROW 40                    // halves per smem row (80B, conflict-free)
#define A_LO_OFF 10240             // 128*80

#define CPA16(dst, src, sz) \
    asm volatile("cp.async.cg.shared.global [%0], [%1], 16, %2;" \
                 :: "r"(dst), "l"(src), "r"(sz))
#define CPA_COMMIT() asm volatile("cp.async.commit_group;" ::: "memory")
#define CPA_WAIT1() asm volatile("cp.async.wait_group 1;" ::: "memory")
#define CPA_WAIT0() asm volatile("cp.async.wait_group 0;" ::: "memory")

#define LDSM4(r, addr) \
    asm volatile("ldmatrix.sync.aligned.m8n8.x4.shared.b16 {%0,%1,%2,%3}, [%4];" \
                 : "=r"((r)[0]), "=r"((r)[1]), "=r"((r)[2]), "=r"((r)[3]) \
                 : "r"(addr))

#define MMAF16(c, a, b0_, b1_) \
    asm volatile("mma.sync.aligned.m16n8k16.row.col.f32.f16.f16.f32 " \
                 "{%0,%1,%2,%3}, {%4,%5,%6,%7}, {%8,%9}, {%0,%1,%2,%3};" \
                 : "+f"((c)[0]), "+f"((c)[1]), "+f"((c)[2]), "+f"((c)[3]) \
                 : "r"((a)[0]), "r"((a)[1]), "r"((a)[2]), "r"((a)[3]), \
                   "r"(b0_), "r"(b1_))

template <int KD, int ND, bool PH1, bool ALO>
__global__ __launch_bounds__(256, 2)
void gemm_f16(const __half* __restrict__ Ahi_,
              const __half* __restrict__ Alo_,
              const __half* __restrict__ Bhi_) {
    constexpr int B_OFF = ALO ? 20480 : 10240;   // after A tiles
    constexpr int SSTG = B_OFF + 10240;          // + B tile (128*80)

    extern __shared__ __align__(16) unsigned char smem[];
    int e = blockIdx.z;
    int count = g_cnt[e];
    int m0 = blockIdx.y * TM;
    if (m0 >= count) return;
    int n0 = blockIdx.x * TN;
    int base = g_base[e];

    const __half* Bhi = Bhi_ + (size_t)e * KD * ND;

    int tid = threadIdx.x;
    int lane = tid & 31;
    int wid = tid >> 5;
    int warp_m = wid & 3;
    int warp_n = wid >> 2;
    uint32_t sb = smem_u32(smem);

    // --- cp.async loader mapping (A and B identical: 128 rows x 64B) ---
    int lrow = tid >> 1;                 // tile row 0..127
    int lhalf = tid & 1;                 // which 32B half of the 64B row

    int am = m0 + lrow;
    bool av = am < count;
    int gidx = 0;
    if (av) gidx = PH1 ? g_perm[base + am] : (base + am);
    uint32_t asz = av ? 16u : 0u;
    const __half* a_hi_src = Ahi_ + (size_t)gidx * KD + lhalf * 16;
    const __half* a_lo_src = Alo_ + (size_t)gidx * KD + lhalf * 16;
    const __half* b_hi_src = Bhi + (size_t)(n0 + lrow) * KD + lhalf * 16;

    uint32_t row_dst = sb + lrow * (SROW * 2) + lhalf * 32;

    // --- ldmatrix lane addresses (relative to stage base) ---
    uint32_t arow_l = (uint32_t)(warp_m * 32 + (lane & 7) + ((lane >> 3) & 1) * 8);
    uint32_t akoff = (uint32_t)((lane >> 4) * 8);
    uint32_t a_ld = sb + (arow_l * SROW + akoff) * 2;
    uint32_t brow_l = (uint32_t)(warp_n * 64 + (lane & 7) + (lane >> 4) * 8);
    uint32_t bkoff = (uint32_t)(((lane >> 3) & 1) * 8);
    uint32_t b_ld = sb + B_OFF + (brow_l * SROW + bkoff) * 2;

    float acc[2][8][4];
#pragma unroll
    for (int i = 0; i < 2; i++)
#pragma unroll
        for (int j = 0; j < 8; j++)
#pragma unroll
            for (int q = 0; q < 4; q++) acc[i][j][q] = 0.0f;

    auto issue = [&](int s, int k0) {
        uint32_t d = row_dst + s * SSTG;
        CPA16(d,      a_hi_src + k0,     asz);
        CPA16(d + 16, a_hi_src + k0 + 8, asz);
        if (ALO) {
            CPA16(d + A_LO_OFF,      a_lo_src + k0,     asz);
            CPA16(d + A_LO_OFF + 16, a_lo_src + k0 + 8, asz);
        }
        CPA16(d + B_OFF,      b_hi_src + k0,     16u);
        CPA16(d + B_OFF + 16, b_hi_src + k0 + 8, 16u);
    };

    const int NCH = KD / TKC;
    issue(0, 0);
    CPA_COMMIT();
    issue(1, TKC);
    CPA_COMMIT();

    int s = 0;
    for (int c = 0; c < NCH; c++) {
        if (c < NCH - 1) CPA_WAIT1(); else CPA_WAIT0();
        __syncthreads();
        if (c + 2 < NCH) {
            int ns = s + 2; if (ns >= 3) ns -= 3;
            issue(ns, (c + 2) * TKC);
            CPA_COMMIT();
        }

        uint32_t abase = a_ld + s * SSTG;
        uint32_t bbase = b_ld + s * SSTG;
#pragma unroll
        for (int ks = 0; ks < 2; ks++) {
            uint32_t ah0[4], ah1[4], al0[4], al1[4];
            uint32_t aad = abase + ks * 32;
            LDSM4(ah0, aad);
            LDSM4(ah1, aad + 16 * SROW * 2);
            if (ALO) {
                LDSM4(al0, aad + A_LO_OFF);
                LDSM4(al1, aad + A_LO_OFF + 16 * SROW * 2);
            }
#pragma unroll
            for (int np = 0; np < 4; np++) {
                uint32_t bh[4];
                LDSM4(bh, bbase + ks * 32 + np * 16 * SROW * 2);

                MMAF16(acc[0][np * 2 + 0], ah0, bh[0], bh[1]);
                MMAF16(acc[0][np * 2 + 1], ah0, bh[2], bh[3]);
                MMAF16(acc[1][np * 2 + 0], ah1, bh[0], bh[1]);
                MMAF16(acc[1][np * 2 + 1], ah1, bh[2], bh[3]);
                if (ALO) {
                    MMAF16(acc[0][np * 2 + 0], al0, bh[0], bh[1]);
                    MMAF16(acc[0][np * 2 + 1], al0, bh[2], bh[3]);
                    MMAF16(acc[1][np * 2 + 0], al1, bh[0], bh[1]);
                    MMAF16(acc[1][np * 2 + 1], al1, bh[2], bh[3]);
                }
            }
        }
        if (++s >= 3) s = 0;
    }

    // epilogue
    int g = lane >> 2, t4 = lane & 3;
#pragma unroll
    for (int mt = 0; mt < 2; mt++) {
        int mr = m0 + warp_m * 32 + mt * 16 + g;
#pragma unroll
        for (int nt = 0; nt < 8; nt++) {
            int col = n0 + warp_n * 64 + nt * 8 + 2 * t4;
            float2 v0, v1;
            v0.x = acc[mt][nt][0]; v0.y = acc[mt][nt][1];
            v1.x = acc[mt][nt][2]; v1.y = acc[mt][nt][3];
            if (PH1) {
                v0.x = fmaxf(v0.x, 0.f); v0.x *= v0.x;
                v0.y = fmaxf(v0.y, 0.f); v0.y *= v0.y;
                v1.x = fmaxf(v1.x, 0.f); v1.x *= v1.x;
                v1.y = fmaxf(v1.y, 0.f); v1.y *= v1.y;
                if (mr < count) {
                    size_t o = (size_t)(base + mr) * ND + col;
                    *(uint32_t*)(g_hhi + o) =
                        packh2(__float2half_rn(v0.x), __float2half_rn(v0.y));
                }
                if (mr + 8 < count) {
                    size_t o = (size_t)(base + mr + 8) * ND + col;
                    *(uint32_t*)(g_hhi + o) =
                        packh2(__float2half_rn(v1.x), __float2half_rn(v1.y));
                }
            } else {
                if (mr < count)
                    *(float2*)(g_yp + (size_t)(base + mr) * ND + col) = v0;
                if (mr + 8 < count)
                    *(float2*)(g_yp + (size_t)(base + mr + 8) * ND + col) = v1;
            }
        }
    }
}

// ---------------- combine ----------------------------------------------------
__global__ void combine_kernel(float* __restrict__ out, int out_size) {
    const int nv = DDIM / 4;
    int t = blockIdx.x * blockDim.x + threadIdx.x;
    if (t < NTOK * nv) {
        int n = t / nv, dv = t % nv;
        int s0 = g_slotof[2 * n], s1 = g_slotof[2 * n + 1];
        float w0 = g_ew[2 * n], w1 = g_ew[2 * n + 1];
        const float4* yp = (const float4*)g_yp;
        float4 a = yp[(size_t)s0 * nv + dv];
        float4 b = yp[(size_t)s1 * nv + dv];
        float4 r;
        r.x = w0 * a.x + w1 * b.x;
        r.y = w0 * a.y + w1 * b.y;
        r.z = w0 * a.z + w1 * b.z;
        r.w = w0 * a.w + w1 * b.w;
        ((float4*)out)[t] = r;
    }
    if (t == 0) {
        for (int idx = NTOK * DDIM; idx < out_size; idx++) out[idx] = g_loss;
    }
}

// ---------------- launch -----------------------------------------------------
extern "C" void kernel_launch(void* const* d_in, const int* in_sizes, int n_in,
                              void* d_out, int out_size) {
    const float* x   = (const float*)d_in[0];
    const float* wg  = (const float*)d_in[1];
    const float* wfc = (const float*)d_in[2];
    const float* wpj = (const float*)d_in[3];
    float* out = (float*)d_out;

    const int smem1 = 3 * (20480 + 10240);   // 92160
    const int smem2 = 3 * (10240 + 10240);   // 61440
    cudaFuncSetAttribute(gemm_f16<DDIM, HDIM, true, true>,
                         cudaFuncAttributeMaxDynamicSharedMemorySize, smem1);
    cudaFuncSetAttribute(gemm_f16<HDIM, DDIM, false, false>,
                         cudaFuncAttributeMaxDynamicSharedMemorySize, smem2);

    __half *xhi, *xlo, *fchi, *pjhi, *hhi;
    cudaGetSymbolAddress((void**)&xhi, g_xhi);
    cudaGetSymbolAddress((void**)&xlo, g_xlo);
    cudaGetSymbolAddress((void**)&fchi, g_fchi);
    cudaGetSymbolAddress((void**)&pjhi, g_pjhi);
    cudaGetSymbolAddress((void**)&hhi, g_hhi);

    init_kernel<<<1, 32>>>();
    convert_hl_kernel<<<1184, 256>>>(x, xhi, xlo, NTOK * DDIM / 4);
    convert_hi_kernel<<<1184, 256>>>(wfc, fchi, NEXP * HDIM * DDIM / 4);
    convert_hi_kernel<<<1184, 256>>>(wpj, pjhi, NEXP * DDIM * HDIM / 4);
    gating_kernel<<<NTOK / 4, 128>>>(x, wg);
    prefix_kernel<<<1, 32>>>();
    scatter_kernel<<<(NSLOT + 255) / 256, 256>>>();

    dim3 g1(HDIM / TN, NSLOT / TM, NEXP);   // 32 x 64 x 8
    gemm_f16<DDIM, HDIM, true, true><<<g1, 256, smem1>>>(xhi, xlo, fchi);

    dim3 g2(DDIM / TN, NSLOT / TM, NEXP);   // 8 x 64 x 8
    gemm_f16<HDIM, DDIM, false, false><<<g2, 256, smem2>>>(hhi, hhi, pjhi);

    combine_kernel<<<(NTOK * DDIM / 4 + 255) / 256, 256>>>(out, out_size);
}

// round 16
// speedup vs baseline: 3.3905x; 1.2116x over previous
#include <cuda_runtime.h>
#include <cuda_fp16.h>
#include <cstdint>

// Problem constants (B=2, T=2048 -> N=4096 tokens)
#define NTOK 4096
#define DDIM 1024
#define HDIM 4096
#define NEXP 8
#define NSLOT (NTOK * 2)

// ---------------- scratch (static device globals; no allocation) ------------
__device__ __half g_xhi[(size_t)NTOK * DDIM];
__device__ __half g_fchi[(size_t)NEXP * HDIM * DDIM];
__device__ __half g_pjhi[(size_t)NEXP * DDIM * HDIM];
__device__ __half g_hhi[(size_t)NSLOT * HDIM];
__device__ float g_yp[(size_t)NSLOT * DDIM];
__device__ int   g_eidx[NSLOT];
__device__ float g_ew[NSLOT];
__device__ int   g_pos[NSLOT];
__device__ int   g_slotof[NSLOT];
__device__ int   g_perm[NSLOT];
__device__ int   g_cnt[NEXP];
__device__ int   g_base[NEXP];
__device__ float g_sump[NEXP];
__device__ float g_loss;

// ---------------- helpers ----------------------------------------------------
__device__ __forceinline__ uint32_t smem_u32(const void* p) {
    uint32_t a;
    asm("{ .reg .u64 t; cvta.to.shared.u64 t, %1; cvt.u32.u64 %0, t; }"
        : "=r"(a) : "l"(p));
    return a;
}

__device__ __forceinline__ uint32_t packh2(__half x, __half y) {
    __half2 h2 = __halves2half2(x, y);
    return *(uint32_t*)&h2;
}

// ---------------- fp16 conversion --------------------------------------------
__global__ void convert_hi_kernel(const float* __restrict__ src,
                                  __half* __restrict__ hi, int n4) {
    int i = blockIdx.x * blockDim.x + threadIdx.x;
    int stride = gridDim.x * blockDim.x;
    for (; i < n4; i += stride) {
        float4 v = ((const float4*)src)[i];
        uint32_t h0 = packh2(__float2half_rn(v.x), __float2half_rn(v.y));
        uint32_t h1 = packh2(__float2half_rn(v.z), __float2half_rn(v.w));
        ((uint2*)hi)[i] = make_uint2(h0, h1);
    }
}

// ---------------- init -------------------------------------------------------
__global__ void init_kernel() {
    int t = threadIdx.x;
    if (t < NEXP) { g_cnt[t] = 0; g_sump[t] = 0.0f; }
}

// ---------------- gating: 1 warp per token -----------------------------------
__global__ void gating_kernel(const float* __restrict__ x,
                              const float* __restrict__ wg) {
    int warp = (blockIdx.x * blockDim.x + threadIdx.x) >> 5;
    int lane = threadIdx.x & 31;
    if (warp >= NTOK) return;
    const float* xr = x + (size_t)warp * DDIM;

    float acc[NEXP];
#pragma unroll
    for (int e = 0; e < NEXP; e++) acc[e] = 0.0f;

    for (int d = lane; d < DDIM; d += 32) {
        float xv = xr[d];
#pragma unroll
        for (int e = 0; e < NEXP; e++) acc[e] += xv * wg[e * DDIM + d];
    }
#pragma unroll
    for (int e = 0; e < NEXP; e++) {
#pragma unroll
        for (int o = 16; o > 0; o >>= 1)
            acc[e] += __shfl_xor_sync(0xFFFFFFFFu, acc[e], o);
    }

    if (lane == 0) {
        float mx = acc[0];
#pragma unroll
        for (int e = 1; e < NEXP; e++) mx = fmaxf(mx, acc[e]);
        float p[NEXP], s = 0.0f;
#pragma unroll
        for (int e = 0; e < NEXP; e++) { p[e] = __expf(acc[e] - mx); s += p[e]; }
        float inv = 1.0f / s;
#pragma unroll
        for (int e = 0; e < NEXP; e++) p[e] *= inv;

#pragma unroll
        for (int e = 0; e < NEXP; e++) atomicAdd(&g_sump[e], p[e]);

        int i0 = 0;
#pragma unroll
        for (int e = 1; e < NEXP; e++) if (p[e] > p[i0]) i0 = e;
        int i1 = (i0 == 0) ? 1 : 0;
#pragma unroll
        for (int e = 0; e < NEXP; e++) if (e != i0 && p[e] > p[i1]) i1 = e;

        float w0 = p[i0], w1 = p[i1];
        float rinv = 1.0f / (w0 + w1);
        w0 *= rinv; w1 *= rinv;

        g_eidx[2 * warp + 0] = i0;
        g_eidx[2 * warp + 1] = i1;
        g_ew[2 * warp + 0] = w0;
        g_ew[2 * warp + 1] = w1;
        g_pos[2 * warp + 0] = atomicAdd(&g_cnt[i0], 1);
        g_pos[2 * warp + 1] = atomicAdd(&g_cnt[i1], 1);
    }
}

// ---------------- prefix + balance loss --------------------------------------
__global__ void prefix_kernel() {
    if (threadIdx.x == 0) {
        int b = 0;
        float loss = 0.0f;
        for (int e = 0; e < NEXP; e++) {
            g_base[e] = b;
            b += g_cnt[e];
            loss += g_sump[e] * (float)g_cnt[e];
        }
        g_loss = loss * (float)NEXP / ((float)NTOK * (float)NTOK);
    }
}

// ---------------- scatter ----------------------------------------------------
__global__ void scatter_kernel() {
    int t = blockIdx.x * blockDim.x + threadIdx.x;
    if (t < NSLOT) {
        int e = g_eidx[t];
        int slot = g_base[e] + g_pos[t];
        g_slotof[t] = slot;
        g_perm[slot] = t >> 1;
    }
}

// ---------------- fp16 mma.sync grouped GEMM, 3-stage cp.async pipeline ------
// D[m,n] = sum_k A[m,k]*B[n,k], all operands fp16 (rn), fp32 accumulate.
// CTA tile 128x128, K chunk 32, 8 warps 4(M)x2(N), warp tile 32x64.
// 3-stage SMEM pipeline, ONE __syncthreads per chunk.
#define TM 128
#define TN 128
#define TKC 32
#define SROW 40                    // halves per smem row (80B, conflict-free)
#define B_OFF 10240                // after A tile (128*80)
#define SSTG 20480                 // + B tile (128*80)
#define SMEM_DYN (3 * SSTG)        // 61440

#define CPA16(dst, src, sz) \
    asm volatile("cp.async.cg.shared.global [%0], [%1], 16, %2;" \
                 :: "r"(dst), "l"(src), "r"(sz))
#define CPA_COMMIT() asm volatile("cp.async.commit_group;" ::: "memory")
#define CPA_WAIT1() asm volatile("cp.async.wait_group 1;" ::: "memory")
#define CPA_WAIT0() asm volatile("cp.async.wait_group 0;" ::: "memory")

#define LDSM4(r, addr) \
    asm volatile("ldmatrix.sync.aligned.m8n8.x4.shared.b16 {%0,%1,%2,%3}, [%4];" \
                 : "=r"((r)[0]), "=r"((r)[1]), "=r"((r)[2]), "=r"((r)[3]) \
                 : "r"(addr))

#define MMAF16(c, a, b0_, b1_) \
    asm volatile("mma.sync.aligned.m16n8k16.row.col.f32.f16.f16.f32 " \
                 "{%0,%1,%2,%3}, {%4,%5,%6,%7}, {%8,%9}, {%0,%1,%2,%3};" \
                 : "+f"((c)[0]), "+f"((c)[1]), "+f"((c)[2]), "+f"((c)[3]) \
                 : "r"((a)[0]), "r"((a)[1]), "r"((a)[2]), "r"((a)[3]), \
                   "r"(b0_), "r"(b1_))

template <int KD, int ND, bool PH1>
__global__ __launch_bounds__(256, 2)
void gemm_f16(const __half* __restrict__ Ahi_,
              const __half* __restrict__ Bhi_) {
    extern __shared__ __align__(16) unsigned char smem[];
    int e = blockIdx.z;
    int count = g_cnt[e];
    int m0 = blockIdx.y * TM;
    if (m0 >= count) return;
    int n0 = blockIdx.x * TN;
    int base = g_base[e];

    const __half* Bhi = Bhi_ + (size_t)e * KD * ND;

    int tid = threadIdx.x;
    int lane = tid & 31;
    int wid = tid >> 5;
    int warp_m = wid & 3;
    int warp_n = wid >> 2;
    uint32_t sb = smem_u32(smem);

    // --- cp.async loader mapping (A and B identical: 128 rows x 64B) ---
    int lrow = tid >> 1;                 // tile row 0..127
    int lhalf = tid & 1;                 // which 32B half of the 64B row

    int am = m0 + lrow;
    bool av = am < count;
    int gidx = 0;
    if (av) gidx = PH1 ? g_perm[base + am] : (base + am);
    uint32_t asz = av ? 16u : 0u;
    const __half* a_hi_src = Ahi_ + (size_t)gidx * KD + lhalf * 16;
    const __half* b_hi_src = Bhi + (size_t)(n0 + lrow) * KD + lhalf * 16;

    uint32_t row_dst = sb + lrow * (SROW * 2) + lhalf * 32;

    // --- ldmatrix lane addresses (relative to stage base) ---
    uint32_t arow_l = (uint32_t)(warp_m * 32 + (lane & 7) + ((lane >> 3) & 1) * 8);
    uint32_t akoff = (uint32_t)((lane >> 4) * 8);
    uint32_t a_ld = sb + (arow_l * SROW + akoff) * 2;
    uint32_t brow_l = (uint32_t)(warp_n * 64 + (lane & 7) + (lane >> 4) * 8);
    uint32_t bkoff = (uint32_t)(((lane >> 3) & 1) * 8);
    uint32_t b_ld = sb + B_OFF + (brow_l * SROW + bkoff) * 2;

    float acc[2][8][4];
#pragma unroll
    for (int i = 0; i < 2; i++)
#pragma unroll
        for (int j = 0; j < 8; j++)
#pragma unroll
            for (int q = 0; q < 4; q++) acc[i][j][q] = 0.0f;

    auto issue = [&](int s, int k0) {
        uint32_t d = row_dst + s * SSTG;
        CPA16(d,      a_hi_src + k0,     asz);
        CPA16(d + 16, a_hi_src + k0 + 8, asz);
        CPA16(d + B_OFF,      b_hi_src + k0,     16u);
        CPA16(d + B_OFF + 16, b_hi_src + k0 + 8, 16u);
    };

    const int NCH = KD / TKC;
    issue(0, 0);
    CPA_COMMIT();
    issue(1, TKC);
    CPA_COMMIT();

    int s = 0;
    for (int c = 0; c < NCH; c++) {
        if (c < NCH - 1) CPA_WAIT1(); else CPA_WAIT0();
        __syncthreads();
        if (c + 2 < NCH) {
            int ns = s + 2; if (ns >= 3) ns -= 3;
            issue(ns, (c + 2) * TKC);
            CPA_COMMIT();
        }

        uint32_t abase = a_ld + s * SSTG;
        uint32_t bbase = b_ld + s * SSTG;
#pragma unroll
        for (int ks = 0; ks < 2; ks++) {
            uint32_t ah0[4], ah1[4];
            uint32_t aad = abase + ks * 32;
            LDSM4(ah0, aad);
            LDSM4(ah1, aad + 16 * SROW * 2);
#pragma unroll
            for (int np = 0; np < 4; np++) {
                uint32_t bh[4];
                LDSM4(bh, bbase + ks * 32 + np * 16 * SROW * 2);

                MMAF16(acc[0][np * 2 + 0], ah0, bh[0], bh[1]);
                MMAF16(acc[0][np * 2 + 1], ah0, bh[2], bh[3]);
                MMAF16(acc[1][np * 2 + 0], ah1, bh[0], bh[1]);
                MMAF16(acc[1][np * 2 + 1], ah1, bh[2], bh[3]);
            }
        }
        if (++s >= 3) s = 0;
    }

    // epilogue
    int g = lane >> 2, t4 = lane & 3;
#pragma unroll
    for (int mt = 0; mt < 2; mt++) {
        int mr = m0 + warp_m * 32 + mt * 16 + g;
#pragma unroll
        for (int nt = 0; nt < 8; nt++) {
            int col = n0 + warp_n * 64 + nt * 8 + 2 * t4;
            float2 v0, v1;
            v0.x = acc[mt][nt][0]; v0.y = acc[mt][nt][1];
            v1.x = acc[mt][nt][2]; v1.y = acc[mt][nt][3];
            if (PH1) {
                v0.x = fmaxf(v0.x, 0.f); v0.x *= v0.x;
                v0.y = fmaxf(v0.y, 0.f); v0.y *= v0.y;
                v1.x = fmaxf(v1.x, 0.f); v1.x *= v1.x;
                v1.y = fmaxf(v1.y, 0.f); v1.y *= v1.y;
                if (mr < count) {
                    size_t o = (size_t)(base + mr) * ND + col;
                    *(uint32_t*)(g_hhi + o) =
                        packh2(__float2half_rn(v0.x), __float2half_rn(v0.y));
                }
                if (mr + 8 < count) {
                    size_t o = (size_t)(base + mr + 8) * ND + col;
                    *(uint32_t*)(g_hhi + o) =
                        packh2(__float2half_rn(v1.x), __float2half_rn(v1.y));
                }
            } else {
                if (mr < count)
                    *(float2*)(g_yp + (size_t)(base + mr) * ND + col) = v0;
                if (mr + 8 < count)
                    *(float2*)(g_yp + (size_t)(base + mr + 8) * ND + col) = v1;
            }
        }
    }
}

// ---------------- combine ----------------------------------------------------
__global__ void combine_kernel(float* __restrict__ out, int out_size) {
    const int nv = DDIM / 4;
    int t = blockIdx.x * blockDim.x + threadIdx.x;
    if (t < NTOK * nv) {
        int n = t / nv, dv = t % nv;
        int s0 = g_slotof[2 * n], s1 = g_slotof[2 * n + 1];
        float w0 = g_ew[2 * n], w1 = g_ew[2 * n + 1];
        const float4* yp = (const float4*)g_yp;
        float4 a = yp[(size_t)s0 * nv + dv];
        float4 b = yp[(size_t)s1 * nv + dv];
        float4 r;
        r.x = w0 * a.x + w1 * b.x;
        r.y = w0 * a.y + w1 * b.y;
        r.z = w0 * a.z + w1 * b.z;
        r.w = w0 * a.w + w1 * b.w;
        ((float4*)out)[t] = r;
    }
    if (t == 0) {
        for (int idx = NTOK * DDIM; idx < out_size; idx++) out[idx] = g_loss;
    }
}

// ---------------- launch -----------------------------------------------------
extern "C" void kernel_launch(void* const* d_in, const int* in_sizes, int n_in,
                              void* d_out, int out_size) {
    const float* x   = (const float*)d_in[0];
    const float* wg  = (const float*)d_in[1];
    const float* wfc = (const float*)d_in[2];
    const float* wpj = (const float*)d_in[3];
    float* out = (float*)d_out;

    cudaFuncSetAttribute(gemm_f16<DDIM, HDIM, true>,
                         cudaFuncAttributeMaxDynamicSharedMemorySize, SMEM_DYN);
    cudaFuncSetAttribute(gemm_f16<HDIM, DDIM, false>,
                         cudaFuncAttributeMaxDynamicSharedMemorySize, SMEM_DYN);

    __half *xhi, *fchi, *pjhi, *hhi;
    cudaGetSymbolAddress((void**)&xhi, g_xhi);
    cudaGetSymbolAddress((void**)&fchi, g_fchi);
    cudaGetSymbolAddress((void**)&pjhi, g_pjhi);
    cudaGetSymbolAddress((void**)&hhi, g_hhi);

    init_kernel<<<1, 32>>>();
    convert_hi_kernel<<<1184, 256>>>(x, xhi, NTOK * DDIM / 4);
    convert_hi_kernel<<<1184, 256>>>(wfc, fchi, NEXP * HDIM * DDIM / 4);
    convert_hi_kernel<<<1184, 256>>>(wpj, pjhi, NEXP * DDIM * HDIM / 4);
    gating_kernel<<<NTOK / 4, 128>>>(x, wg);
    prefix_kernel<<<1, 32>>>();
    scatter_kernel<<<(NSLOT + 255) / 256, 256>>>();

    dim3 g1(HDIM / TN, NSLOT / TM, NEXP);   // 32 x 64 x 8
    gemm_f16<DDIM, HDIM, true><<<g1, 256, SMEM_DYN>>>(xhi, fchi);

    dim3 g2(DDIM / TN, NSLOT / TM, NEXP);   // 8 x 64 x 8
    gemm_f16<HDIM, DDIM, false><<<g2, 256, SMEM_DYN>>>(hhi, pjhi);

    combine_kernel<<<(NTOK * DDIM / 4 + 255) / 256, 256>>>(out, out_size);
}